// round 2
// baseline (speedup 1.0000x reference)
#include <cuda_runtime.h>
#include <math.h>

// ---------------- problem constants ----------------
#define B_   32768
#define T_   7
#define EIN  60
#define DIN  36
#define U_   356
#define G_   1424          // 4*U
#define H1_  768
#define OUT_ 168

// ---------------- scratch (device globals; total < 2 GB!) ------------------
__device__ __align__(16) float g_zr  [(size_t)B_ * G_];      // h@R        187 MB
__device__ __align__(16) float g_zx  [(size_t)B_ * G_];      // x_t@K + b  187 MB
__device__ __align__(16) float g_h   [(size_t)B_ * U_];      //  46.7 MB
__device__ __align__(16) float g_c   [(size_t)B_ * U_];      //  46.7 MB
__device__ __align__(16) float g_dec [(size_t)B_ * T_ * U_]; // 327 MB
__device__ __align__(16) float g_b1  [(size_t)B_ * H1_];     // 100 MB
__device__ __align__(16) float g_b2  [(size_t)B_ * H1_];     // 100 MB

// ---------------- generic SGEMM: C = act(A@B + bias) -----------------------
// A: row-major [M,K] (lda), B: row-major [K,N] (ldb), C: row-major (ldc)
// 128x128 block tile, BK=8, 256 threads, 8x8 per-thread microtile.
// Call-site contract: lda%4==0, ldb%4==0, N%4==0, K%4==0, 16B-aligned bases.
template<int ACT>  // 0 = none, 1 = relu, 2 = tanh
__global__ void __launch_bounds__(256, 2)
sgemm_kernel(const float* __restrict__ A, int lda,
             const float* __restrict__ Bm, int ldb,
             float* __restrict__ C, int ldc,
             const float* __restrict__ bias,
             int M, int N, int K)
{
    __shared__ float As[8][132];
    __shared__ float Bs[8][132];

    const int tid = threadIdx.x;
    const int m0 = blockIdx.y * 128;
    const int n0 = blockIdx.x * 128;

    const int ar = tid >> 1;         // 0..127
    const int ac = (tid & 1) * 4;    // 0 or 4
    const int br = tid >> 5;         // 0..7
    const int bc = (tid & 31) * 4;   // 0..124

    const int ty = tid >> 4;
    const int tx = tid & 15;
    const int my = ty * 8;
    const int nx = tx * 8;

    float acc[8][8];
#pragma unroll
    for (int i = 0; i < 8; i++)
#pragma unroll
        for (int j = 0; j < 8; j++) acc[i][j] = 0.f;

    for (int k0 = 0; k0 < K; k0 += 8) {
        float4 av = make_float4(0.f, 0.f, 0.f, 0.f);
        if ((m0 + ar) < M && (k0 + ac) < K)
            av = *reinterpret_cast<const float4*>(
                     &A[(size_t)(m0 + ar) * lda + (k0 + ac)]);
        As[ac + 0][ar] = av.x;
        As[ac + 1][ar] = av.y;
        As[ac + 2][ar] = av.z;
        As[ac + 3][ar] = av.w;

        float4 bv = make_float4(0.f, 0.f, 0.f, 0.f);
        if ((k0 + br) < K && (n0 + bc) < N)
            bv = *reinterpret_cast<const float4*>(
                     &Bm[(size_t)(k0 + br) * ldb + (n0 + bc)]);
        *reinterpret_cast<float4*>(&Bs[br][bc]) = bv;

        __syncthreads();

#pragma unroll
        for (int k = 0; k < 8; k++) {
            float ra[8], rb[8];
            float4 a0 = *reinterpret_cast<const float4*>(&As[k][my]);
            float4 a1 = *reinterpret_cast<const float4*>(&As[k][my + 4]);
            float4 b0 = *reinterpret_cast<const float4*>(&Bs[k][nx]);
            float4 b1 = *reinterpret_cast<const float4*>(&Bs[k][nx + 4]);
            ra[0]=a0.x; ra[1]=a0.y; ra[2]=a0.z; ra[3]=a0.w;
            ra[4]=a1.x; ra[5]=a1.y; ra[6]=a1.z; ra[7]=a1.w;
            rb[0]=b0.x; rb[1]=b0.y; rb[2]=b0.z; rb[3]=b0.w;
            rb[4]=b1.x; rb[5]=b1.y; rb[6]=b1.z; rb[7]=b1.w;
#pragma unroll
            for (int i = 0; i < 8; i++)
#pragma unroll
                for (int j = 0; j < 8; j++)
                    acc[i][j] = fmaf(ra[i], rb[j], acc[i][j]);
        }
        __syncthreads();
    }

#pragma unroll
    for (int i = 0; i < 8; i++) {
        const int m = m0 + my + i;
        if (m >= M) continue;
#pragma unroll
        for (int j = 0; j < 8; j++) {
            const int n = n0 + nx + j;
            if (n >= N) continue;
            float v = acc[i][j];
            if (bias) v += bias[n];
            if (ACT == 1) v = fmaxf(v, 0.f);
            if (ACT == 2) v = tanhf(v);
            C[(size_t)m * ldc + n] = v;
        }
    }
}

// ---------------- LSTM cell (elementwise) -----------------------------
// zr: [B,4U] recurrent contribution h@R
// zx: [B,4U] input contribution x_t@K + b
// h,c: [B,U] state (updated in place)
// hs: optional per-step output store at b*(T*U) + hs_off + u
__global__ void lstm_cell_kernel(const float* __restrict__ zr,
                                 const float* __restrict__ zx,
                                 float* __restrict__ h,
                                 float* __restrict__ c,
                                 float* __restrict__ hs, int hs_off)
{
    const int idx = blockIdx.x * blockDim.x + threadIdx.x;
    if (idx >= B_ * U_) return;
    const int b = idx / U_;
    const int u = idx - b * U_;

    const float* r = zr + (size_t)b * G_;
    const float* x = zx + (size_t)b * G_;

    const float zi = r[u         ] + x[u         ];
    const float zf = r[u +     U_] + x[u +     U_];
    const float zg = r[u + 2 * U_] + x[u + 2 * U_];
    const float zo = r[u + 3 * U_] + x[u + 3 * U_];

    const float iv = 1.f / (1.f + expf(-zi));
    const float fv = 1.f / (1.f + expf(-zf));
    const float gv = tanhf(zg);
    const float ov = 1.f / (1.f + expf(-zo));

    const float cn = fv * c[idx] + iv * gv;
    const float hn = ov * tanhf(cn);

    c[idx] = cn;
    h[idx] = hn;
    if (hs) hs[(size_t)b * (T_ * U_) + hs_off + u] = hn;
}

__global__ void zero2_kernel(float* a, float* b, int n)
{
    const int i = blockIdx.x * blockDim.x + threadIdx.x;
    if (i < n) { a[i] = 0.f; b[i] = 0.f; }
}

// ---------------- host orchestration ----------------------------------
static inline dim3 gemm_grid(int M, int N)
{
    return dim3((N + 127) / 128, (M + 127) / 128);
}

extern "C" void kernel_launch(void* const* d_in, const int* in_sizes, int n_in,
                              void* d_out, int out_size)
{
    const float* x    = (const float*)d_in[0];   // [B,T,60]
    const float* m    = (const float*)d_in[1];   // [B,T,36]
    const float* encK = (const float*)d_in[2];   // [60,1424]
    const float* encR = (const float*)d_in[3];   // [356,1424]
    const float* encB = (const float*)d_in[4];   // [1424]
    const float* decK = (const float*)d_in[5];   // [36,1424]
    const float* decR = (const float*)d_in[6];   // [356,1424]
    const float* decB = (const float*)d_in[7];   // [1424]
    const float* Wmap = (const float*)d_in[8];   // [2492,768]
    const float* bmap = (const float*)d_in[9];
    const float* W1   = (const float*)d_in[10];  // [768,768]
    const float* b1   = (const float*)d_in[11];
    const float* W2   = (const float*)d_in[12];  // [768,768]
    const float* b2   = (const float*)d_in[13];
    const float* Wo   = (const float*)d_in[14];  // [768,168]
    const float* bo   = (const float*)d_in[15];
    float* out = (float*)d_out;                  // [B,168]

    float *zr, *zx, *h, *c, *dec, *t1, *t2;
    cudaGetSymbolAddress((void**)&zr,  g_zr);
    cudaGetSymbolAddress((void**)&zx,  g_zx);
    cudaGetSymbolAddress((void**)&h,   g_h);
    cudaGetSymbolAddress((void**)&c,   g_c);
    cudaGetSymbolAddress((void**)&dec, g_dec);
    cudaGetSymbolAddress((void**)&t1,  g_b1);
    cudaGetSymbolAddress((void**)&t2,  g_b2);

    // zero initial state (globals persist across graph replays; must re-zero)
    {
        const int n = B_ * U_;
        zero2_kernel<<<(n + 255) / 256, 256>>>(h, c, n);
    }

    const int cell_blocks = (B_ * U_ + 255) / 256;
    const dim3 gridG = gemm_grid(B_, G_);

    // encoder: 7 steps, only final (h,c) kept.
    // x_t rows: x + t*EIN, lda = T*EIN (both stride and base 16B-aligned).
    for (int t = 0; t < T_; t++) {
        sgemm_kernel<0><<<gridG, 256>>>(x + (size_t)t * EIN, T_ * EIN,
                                        encK, G_, zx, G_, encB, B_, G_, EIN);
        sgemm_kernel<0><<<gridG, 256>>>(h, U_, encR, G_, zr, G_,
                                        nullptr, B_, G_, U_);
        lstm_cell_kernel<<<cell_blocks, 256>>>(zr, zx, h, c, nullptr, 0);
    }

    // decoder: 7 steps, store hidden sequence into g_dec
    for (int t = 0; t < T_; t++) {
        sgemm_kernel<0><<<gridG, 256>>>(m + (size_t)t * DIN, T_ * DIN,
                                        decK, G_, zx, G_, decB, B_, G_, DIN);
        sgemm_kernel<0><<<gridG, 256>>>(h, U_, decR, G_, zr, G_,
                                        nullptr, B_, G_, U_);
        lstm_cell_kernel<<<cell_blocks, 256>>>(zr, zx, h, c, dec, t * U_);
    }

    // dense head
    sgemm_kernel<1><<<gemm_grid(B_, H1_), 256>>>(dec, T_ * U_, Wmap, H1_,
                                                 t1, H1_, bmap, B_, H1_, T_ * U_);
    sgemm_kernel<2><<<gemm_grid(B_, H1_), 256>>>(t1, H1_, W1, H1_,
                                                 t2, H1_, b1, B_, H1_, H1_);
    sgemm_kernel<2><<<gemm_grid(B_, H1_), 256>>>(t2, H1_, W2, H1_,
                                                 t1, H1_, b2, B_, H1_, H1_);
    sgemm_kernel<0><<<gemm_grid(B_, OUT_), 256>>>(t1, H1_, Wo, OUT_,
                                                  out, OUT_, bo, B_, OUT_, H1_);
}

// round 4
// speedup vs baseline: 2.7495x; 2.7495x over previous
#include <cuda_runtime.h>
#include <math.h>
#include <stdint.h>

// ---------------- problem constants ----------------
#define B_   32768
#define T_   7
#define EIN  60
#define DIN  36
#define U_   356
#define G_   1424          // 4*U
#define H1_  768
#define OUT_ 168

// ---------------- scratch (device globals; total < 2 GB) -------------------
__device__ __align__(16) float g_zr  [(size_t)B_ * G_];      // h@R        187 MB
__device__ __align__(16) float g_zx  [(size_t)B_ * G_];      // x_t@K + b  187 MB
__device__ __align__(16) float g_h   [(size_t)B_ * U_];
__device__ __align__(16) float g_c   [(size_t)B_ * U_];
__device__ __align__(16) float g_dec [(size_t)B_ * T_ * U_]; // 327 MB
__device__ __align__(16) float g_b1  [(size_t)B_ * H1_];
__device__ __align__(16) float g_b2  [(size_t)B_ * H1_];
// transposed weights pool (K-major [N,K]); offsets in floats
#define WT_ENCK 0                         // [1424,60]
#define WT_ENCR (WT_ENCK + 1424*60)       // [1424,356]
#define WT_DECK (WT_ENCR + 1424*356)      // [1424,36]
#define WT_DECR (WT_DECK + 1424*36)       // [1424,356]
#define WT_MAP  (WT_DECR + 1424*356)      // [768,2492]
#define WT_W1   (WT_MAP  + 768*2492)      // [768,768]
#define WT_W2   (WT_W1   + 768*768)       // [768,768]
#define WT_WO   (WT_W2   + 768*768)       // [168,768]
#define WT_TOTAL (WT_WO + 168*768)
__device__ __align__(16) float g_wT[WT_TOTAL];               // ~17.5 MB

// ==================== tf32 helpers ====================
__device__ __forceinline__ uint32_t f2tf32(float f) {
    uint32_t u;
    asm("cvt.rna.tf32.f32 %0, %1;" : "=r"(u) : "f"(f));
    return u;
}

__device__ __forceinline__ void mma_tf32(float c[4],
                                         uint32_t a0, uint32_t a1,
                                         uint32_t a2, uint32_t a3,
                                         uint32_t b0, uint32_t b1)
{
    asm volatile(
        "mma.sync.aligned.m16n8k8.row.col.f32.tf32.tf32.f32 "
        "{%0,%1,%2,%3}, {%4,%5,%6,%7}, {%8,%9}, {%0,%1,%2,%3};"
        : "+f"(c[0]), "+f"(c[1]), "+f"(c[2]), "+f"(c[3])
        : "r"(a0), "r"(a1), "r"(a2), "r"(a3), "r"(b0), "r"(b1));
}

// ==================== tf32 mma.sync GEMM ====================
// C[M,N] = act(A[M,K] @ Bt[N,K]^T + bias), row-major.
// 128x128 tile, BK=16, 256 threads (8 warps, 2x4; each warp 64x32).
// Contract: M%128==0, K%4==0, 16B-aligned bases, lda/ldb/ldc floats with
// 16B-aligned row strides at k%4 offsets. N arbitrary (guarded).
#define SSTRIDE 20   // smem row stride in words (conflict-free for quad pattern)

template<int ACT> // 0 none, 1 relu, 2 tanh
__global__ void __launch_bounds__(256)
tf32_gemm(const float* __restrict__ A, int lda,
          const float* __restrict__ Bt, int ldb,
          float* __restrict__ C, int ldc,
          const float* __restrict__ bias,
          int M, int N, int K)
{
    __shared__ uint32_t As[2][128 * SSTRIDE];
    __shared__ uint32_t Bs[2][128 * SSTRIDE];

    const int tid  = threadIdx.x;
    const int lane = tid & 31;
    const int w    = tid >> 5;
    const int m0   = blockIdx.y * 128;
    const int n0   = blockIdx.x * 128;

    const int wm = (w >> 2) * 64;   // warp M offset (0,64)
    const int wn = (w & 3) * 32;    // warp N offset (0,32,64,96)
    const int g  = lane >> 2;       // 0..7
    const int q4 = lane & 3;        // 0..3

    // staging mapping: 2 float4 per thread per operand
    const int r0s = tid >> 2;                 // id0 row
    const int k0s = (tid & 3) * 4;            // id0 k
    const int r1s = (tid + 256) >> 2;
    const int k1s = k0s;                      // (tid+256)&3 == tid&3

    float acc[4][4][4];
#pragma unroll
    for (int i = 0; i < 4; i++)
#pragma unroll
        for (int j = 0; j < 4; j++)
#pragma unroll
            for (int q = 0; q < 4; q++) acc[i][j][q] = 0.f;

    const int nck = (K + 15) >> 4;

    // ---- helper lambdas (macros via code) ----
    float4 pa0, pa1, pb0, pb1;
    auto gload = [&](int c) {
        const int k0 = c * 16;
        const float zz = 0.f;
        // A
        {
            const int k = k0 + k0s;
            pa0 = (k < K) ? *reinterpret_cast<const float4*>(
                                &A[(size_t)(m0 + r0s) * lda + k])
                          : make_float4(zz, zz, zz, zz);
            pa1 = (k < K) ? *reinterpret_cast<const float4*>(
                                &A[(size_t)(m0 + r1s) * lda + k])
                          : make_float4(zz, zz, zz, zz);
        }
        // B
        {
            const int k = k0 + k1s;
            const int n_0 = n0 + r0s, n_1 = n0 + r1s;
            pb0 = (k < K && n_0 < N) ? *reinterpret_cast<const float4*>(
                                           &Bt[(size_t)n_0 * ldb + k])
                                     : make_float4(zz, zz, zz, zz);
            pb1 = (k < K && n_1 < N) ? *reinterpret_cast<const float4*>(
                                           &Bt[(size_t)n_1 * ldb + k])
                                     : make_float4(zz, zz, zz, zz);
        }
    };
    auto sstore = [&](int s) {
        uint32_t* a = &As[s][r0s * SSTRIDE + k0s];
        a[0] = f2tf32(pa0.x); a[1] = f2tf32(pa0.y);
        a[2] = f2tf32(pa0.z); a[3] = f2tf32(pa0.w);
        a = &As[s][r1s * SSTRIDE + k1s];
        a[0] = f2tf32(pa1.x); a[1] = f2tf32(pa1.y);
        a[2] = f2tf32(pa1.z); a[3] = f2tf32(pa1.w);
        uint32_t* b = &Bs[s][r0s * SSTRIDE + k0s];
        b[0] = f2tf32(pb0.x); b[1] = f2tf32(pb0.y);
        b[2] = f2tf32(pb0.z); b[3] = f2tf32(pb0.w);
        b = &Bs[s][r1s * SSTRIDE + k1s];
        b[0] = f2tf32(pb1.x); b[1] = f2tf32(pb1.y);
        b[2] = f2tf32(pb1.z); b[3] = f2tf32(pb1.w);
    };

    gload(0);
    sstore(0);
    __syncthreads();

    for (int c = 0; c < nck; c++) {
        const int cur = c & 1;
        if (c + 1 < nck) gload(c + 1);

        // compute from buffer cur: 2 k-groups of 8
#pragma unroll
        for (int kg = 0; kg < 2; kg++) {
            const int kb = kg * 8;
            uint32_t af[4][4], bf[4][2];
#pragma unroll
            for (int mt = 0; mt < 4; mt++) {
                const uint32_t* ar = &As[cur][(wm + mt * 16 + g) * SSTRIDE + kb + q4];
                af[mt][0] = ar[0];
                af[mt][1] = ar[8 * SSTRIDE];
                af[mt][2] = ar[4];
                af[mt][3] = ar[8 * SSTRIDE + 4];
            }
#pragma unroll
            for (int nt = 0; nt < 4; nt++) {
                const uint32_t* br = &Bs[cur][(wn + nt * 8 + g) * SSTRIDE + kb + q4];
                bf[nt][0] = br[0];
                bf[nt][1] = br[4];
            }
#pragma unroll
            for (int mt = 0; mt < 4; mt++)
#pragma unroll
                for (int nt = 0; nt < 4; nt++)
                    mma_tf32(acc[mt][nt],
                             af[mt][0], af[mt][1], af[mt][2], af[mt][3],
                             bf[nt][0], bf[nt][1]);
        }

        if (c + 1 < nck) sstore((c + 1) & 1);
        __syncthreads();
    }

    // ---- epilogue ----
#pragma unroll
    for (int mt = 0; mt < 4; mt++) {
#pragma unroll
        for (int nt = 0; nt < 4; nt++) {
            const int col = n0 + wn + nt * 8 + 2 * q4;
            if (col >= N) continue;
            float2 bsv = make_float2(0.f, 0.f);
            if (bias) { bsv.x = bias[col]; bsv.y = bias[col + 1]; }
#pragma unroll
            for (int half = 0; half < 2; half++) {
                const int row = m0 + wm + mt * 16 + g + half * 8;
                float vx = acc[mt][nt][half * 2 + 0] + bsv.x;
                float vy = acc[mt][nt][half * 2 + 1] + bsv.y;
                if (ACT == 1) { vx = fmaxf(vx, 0.f); vy = fmaxf(vy, 0.f); }
                if (ACT == 2) { vx = tanhf(vx); vy = tanhf(vy); }
                *reinterpret_cast<float2*>(&C[(size_t)row * ldc + col]) =
                    make_float2(vx, vy);
            }
        }
    }
}

// ==================== transpose: out[Cc,R] = in[R,Cc]^T ====================
__global__ void transpose_kernel(const float* __restrict__ in,
                                 float* __restrict__ out, int R, int Cc)
{
    __shared__ float t[32][33];
    const int c0 = blockIdx.x * 32, r0 = blockIdx.y * 32;
    const int x = threadIdx.x, y = threadIdx.y;
#pragma unroll
    for (int dy = 0; dy < 32; dy += 8) {
        const int r = r0 + y + dy, c = c0 + x;
        t[y + dy][x] = (r < R && c < Cc) ? in[(size_t)r * Cc + c] : 0.f;
    }
    __syncthreads();
#pragma unroll
    for (int dy = 0; dy < 32; dy += 8) {
        const int r = c0 + y + dy, c = r0 + x;
        if (r < Cc && c < R) out[(size_t)r * R + c] = t[x][y + dy];
    }
}

// ==================== LSTM cell (elementwise) ====================
__global__ void lstm_cell_kernel(const float* __restrict__ zr,
                                 const float* __restrict__ zx,
                                 float* __restrict__ h,
                                 float* __restrict__ c,
                                 float* __restrict__ hs, int hs_off)
{
    const int idx = blockIdx.x * blockDim.x + threadIdx.x;
    if (idx >= B_ * U_) return;
    const int b = idx / U_;
    const int u = idx - b * U_;

    const float* r = zr + (size_t)b * G_;
    const float* x = zx + (size_t)b * G_;

    const float zi = r[u         ] + x[u         ];
    const float zf = r[u +     U_] + x[u +     U_];
    const float zg = r[u + 2 * U_] + x[u + 2 * U_];
    const float zo = r[u + 3 * U_] + x[u + 3 * U_];

    const float iv = 1.f / (1.f + expf(-zi));
    const float fv = 1.f / (1.f + expf(-zf));
    const float gv = tanhf(zg);
    const float ov = 1.f / (1.f + expf(-zo));

    const float cn = fv * c[idx] + iv * gv;
    const float hn = ov * tanhf(cn);

    c[idx] = cn;
    h[idx] = hn;
    if (hs) hs[(size_t)b * (T_ * U_) + hs_off + u] = hn;
}

__global__ void zero2_kernel(float* a, float* b, int n)
{
    const int i = blockIdx.x * blockDim.x + threadIdx.x;
    if (i < n) { a[i] = 0.f; b[i] = 0.f; }
}

// ==================== host orchestration ====================
static inline dim3 ggrid(int M, int N)
{
    return dim3((N + 127) / 128, M / 128);
}

extern "C" void kernel_launch(void* const* d_in, const int* in_sizes, int n_in,
                              void* d_out, int out_size)
{
    const float* x    = (const float*)d_in[0];
    const float* m    = (const float*)d_in[1];
    const float* encK = (const float*)d_in[2];
    const float* encR = (const float*)d_in[3];
    const float* encB = (const float*)d_in[4];
    const float* decK = (const float*)d_in[5];
    const float* decR = (const float*)d_in[6];
    const float* decB = (const float*)d_in[7];
    const float* Wmap = (const float*)d_in[8];
    const float* bmap = (const float*)d_in[9];
    const float* W1   = (const float*)d_in[10];
    const float* b1   = (const float*)d_in[11];
    const float* W2   = (const float*)d_in[12];
    const float* b2   = (const float*)d_in[13];
    const float* Wo   = (const float*)d_in[14];
    const float* bo   = (const float*)d_in[15];
    float* out = (float*)d_out;

    float *zr, *zx, *h, *c, *dec, *t1, *t2, *wT;
    cudaGetSymbolAddress((void**)&zr,  g_zr);
    cudaGetSymbolAddress((void**)&zx,  g_zx);
    cudaGetSymbolAddress((void**)&h,   g_h);
    cudaGetSymbolAddress((void**)&c,   g_c);
    cudaGetSymbolAddress((void**)&dec, g_dec);
    cudaGetSymbolAddress((void**)&t1,  g_b1);
    cudaGetSymbolAddress((void**)&t2,  g_b2);
    cudaGetSymbolAddress((void**)&wT,  g_wT);

    // transpose all weights to K-major [N,K]
    dim3 tb(32, 8);
    transpose_kernel<<<dim3((G_+31)/32, (EIN+31)/32), tb>>>(encK, wT+WT_ENCK, EIN, G_);
    transpose_kernel<<<dim3((G_+31)/32, (U_ +31)/32), tb>>>(encR, wT+WT_ENCR, U_,  G_);
    transpose_kernel<<<dim3((G_+31)/32, (DIN+31)/32), tb>>>(decK, wT+WT_DECK, DIN, G_);
    transpose_kernel<<<dim3((G_+31)/32, (U_ +31)/32), tb>>>(decR, wT+WT_DECR, U_,  G_);
    transpose_kernel<<<dim3((H1_+31)/32, (T_*U_+31)/32), tb>>>(Wmap, wT+WT_MAP, T_*U_, H1_);
    transpose_kernel<<<dim3((H1_+31)/32, (H1_+31)/32), tb>>>(W1, wT+WT_W1, H1_, H1_);
    transpose_kernel<<<dim3((H1_+31)/32, (H1_+31)/32), tb>>>(W2, wT+WT_W2, H1_, H1_);
    transpose_kernel<<<dim3((OUT_+31)/32, (H1_+31)/32), tb>>>(Wo, wT+WT_WO, H1_, OUT_);

    {
        const int n = B_ * U_;
        zero2_kernel<<<(n + 255) / 256, 256>>>(h, c, n);
    }

    const int cell_blocks = (B_ * U_ + 255) / 256;
    const dim3 grG = ggrid(B_, G_);

    // encoder
    for (int t = 0; t < T_; t++) {
        tf32_gemm<0><<<grG, 256>>>(x + (size_t)t * EIN, T_ * EIN,
                                   wT + WT_ENCK, EIN, zx, G_, encB,
                                   B_, G_, EIN);
        tf32_gemm<0><<<grG, 256>>>(h, U_, wT + WT_ENCR, U_, zr, G_,
                                   nullptr, B_, G_, U_);
        lstm_cell_kernel<<<cell_blocks, 256>>>(zr, zx, h, c, nullptr, 0);
    }
    // decoder
    for (int t = 0; t < T_; t++) {
        tf32_gemm<0><<<grG, 256>>>(m + (size_t)t * DIN, T_ * DIN,
                                   wT + WT_DECK, DIN, zx, G_, decB,
                                   B_, G_, DIN);
        tf32_gemm<0><<<grG, 256>>>(h, U_, wT + WT_DECR, U_, zr, G_,
                                   nullptr, B_, G_, U_);
        lstm_cell_kernel<<<cell_blocks, 256>>>(zr, zx, h, c, dec, t * U_);
    }

    // dense head
    tf32_gemm<1><<<ggrid(B_, H1_), 256>>>(dec, T_ * U_, wT + WT_MAP, T_ * U_,
                                          t1, H1_, bmap, B_, H1_, T_ * U_);
    tf32_gemm<2><<<ggrid(B_, H1_), 256>>>(t1, H1_, wT + WT_W1, H1_,
                                          t2, H1_, b1, B_, H1_, H1_);
    tf32_gemm<2><<<ggrid(B_, H1_), 256>>>(t2, H1_, wT + WT_W2, H1_,
                                          t1, H1_, b2, B_, H1_, H1_);
    tf32_gemm<0><<<ggrid(B_, OUT_), 256>>>(t1, H1_, wT + WT_WO, H1_,
                                           out, OUT_, bo, B_, OUT_, H1_);
}